// round 2
// baseline (speedup 1.0000x reference)
#include <cuda_runtime.h>
#include <stdint.h>

// Problem-scale constants (fixed dataset: T=2048, W=30, N=61440, k=819)
#define NMAX   61440
#define TMAX   2048
#define NB     60          // radix blocks; NB*CHUNK >= NMAX
#define CHUNK  1024        // elements per radix block / greedy chunk

// ---- device-global scratch (no allocations allowed) ----
__device__ unsigned long long g_bufA[NMAX];
__device__ unsigned long long g_bufB[NMAX];
__device__ unsigned int       g_hist[256 * NB];
__device__ unsigned char      g_sel[NMAX];
__device__ int                g_cnt;

// ============================================================
// Kernel 1: build sort keys (descending score+log(mask), tie -> ascending idx)
// key64 = (~sortable_asc(f)) << 32 | idx   -> ascending radix sort gives the order
// ============================================================
__global__ void k_init(const float* __restrict__ scores,
                       const float* __restrict__ mask, int N) {
    int i = blockIdx.x * blockDim.x + threadIdx.x;
    if (i < N) {
        float key = scores[i] + logf(mask[i]);
        unsigned b   = __float_as_uint(key);
        unsigned asc = (b & 0x80000000u) ? ~b : (b | 0x80000000u);
        unsigned dsc = ~asc;
        g_bufA[i] = ((unsigned long long)dsc << 32) | (unsigned)i;
        g_sel[i] = 0;
    }
    if (i == 0) g_cnt = 0;
}

// ============================================================
// LSD radix sort on bits [32..63] of the packed key, 4 passes x 8 bits.
// Stable (pass-wise stable scatter), payload idx rides in low 32 bits.
// ============================================================
__global__ void k_hist(int srcIsA, int N, int shift) {
    const unsigned long long* src = srcIsA ? g_bufA : g_bufB;
    __shared__ unsigned int h[256];
    int t = threadIdx.x;
    h[t] = 0;
    __syncthreads();
    int base = blockIdx.x * CHUNK;
    for (int j = t; j < CHUNK; j += 256) {
        int i = base + j;
        if (i < N) {
            unsigned d = (unsigned)(src[i] >> shift) & 255u;
            atomicAdd(&h[d], 1u);
        }
    }
    __syncthreads();
    g_hist[t * NB + blockIdx.x] = h[t];
}

__global__ void k_scan() {
    // thread t owns bin t: serial exclusive scan over its NB block-counts,
    // then block-level exclusive scan of the 256 bin totals.
    __shared__ unsigned int tot[256];
    int t = threadIdx.x;
    unsigned v[NB];
    unsigned run = 0;
    #pragma unroll
    for (int b = 0; b < NB; b++) v[b] = g_hist[t * NB + b];
    #pragma unroll
    for (int b = 0; b < NB; b++) { unsigned x = v[b]; v[b] = run; run += x; }
    tot[t] = run;
    __syncthreads();
    if (t == 0) {
        unsigned acc = 0;
        for (int i = 0; i < 256; i++) { unsigned x = tot[i]; tot[i] = acc; acc += x; }
    }
    __syncthreads();
    unsigned base = tot[t];
    #pragma unroll
    for (int b = 0; b < NB; b++) g_hist[t * NB + b] = base + v[b];
}

__global__ void k_scatter(int srcIsA, int N, int shift) {
    const unsigned long long* src = srcIsA ? g_bufA : g_bufB;
    unsigned long long*       dst = srcIsA ? g_bufB : g_bufA;
    __shared__ unsigned int   base[256];
    __shared__ unsigned short waveDig[256];
    __shared__ unsigned int   histW[256];
    int t = threadIdx.x;
    base[t]  = g_hist[t * NB + blockIdx.x];
    histW[t] = 0;
    __syncthreads();
    int cbase = blockIdx.x * CHUNK;
    for (int wv = 0; wv < CHUNK / 256; wv++) {
        int i = cbase + wv * 256 + t;
        unsigned long long v = 0ull;
        unsigned d = 0;
        bool ok = (i < N);
        if (ok) {
            v = src[i];
            d = (unsigned)(v >> shift) & 255u;
            waveDig[t] = (unsigned short)d;
            atomicAdd(&histW[d], 1u);
        } else {
            waveDig[t] = 0xFFFFu;  // never matches a digit
        }
        __syncthreads();
        if (ok) {
            unsigned r = 0;
            for (int u = 0; u < t; u++) r += (waveDig[u] == (unsigned short)d);
            dst[base[d] + r] = v;       // stable within wave
        }
        __syncthreads();
        base[t] += histW[t];
        histW[t] = 0;
        __syncthreads();
    }
}

// ============================================================
// Kernel: greedy non-crossing selection (exact, capped at k).
// Chunked speculation: phase-1 checks 1024 candidates in parallel against the
// chunk-start tables (rejection vs a stale table is FINAL — tables are
// monotone toward rejection). Phase-2: warp 0 serially re-validates only the
// survivors against live tables and commits accepts.
// ============================================================
__global__ void __launch_bounds__(CHUNK, 1)
k_greedy(const int* __restrict__ spans, const int* __restrict__ pK, int N) {
    __shared__ int s2e[TMAX], e2s[TMAX];
    __shared__ int sC[CHUNK], eC[CHUNK], cC[CHUNK];
    __shared__ unsigned int mmask[CHUNK / 32];
    __shared__ int sh_cnt, sh_done;

    int t = threadIdx.x;
    for (int i = t; i < TMAX; i += blockDim.x) { s2e[i] = -1; e2s[i] = -1; }
    if (t == 0) { sh_cnt = 0; sh_done = 0; }
    __syncthreads();

    int K = pK ? pK[0] : 819;
    int nch = (N + CHUNK - 1) / CHUNK;

    for (int ch = 0; ch < nch; ch++) {
        if (sh_done) break;  // uniform
        int i = ch * CHUNK + t;
        bool maybe = false;
        int s = 0, e = 0, c = 0;
        if (i < N) {
            c = (int)(unsigned)(g_bufA[i] & 0xFFFFFFFFull);
            s = spans[2 * c];
            e = spans[2 * c + 1];
            bool cross = false;
            int w = e - s;
            for (int d = 1; d <= w; d++)
                if (s2e[s + d] > e) { cross = true; break; }
            if (!cross)
                for (int d = 0; d < w; d++) {
                    int v = e2s[s + d];
                    if (v >= 0 && v < s) { cross = true; break; }
                }
            maybe = !cross;
        }
        sC[t] = s; eC[t] = e; cC[t] = c;
        unsigned bal = __ballot_sync(0xFFFFFFFFu, maybe);
        if ((t & 31) == 0) mmask[t >> 5] = bal;
        __syncthreads();

        if (t < 32) {
            int cnt = sh_cnt;
            for (int g = 0; g < CHUNK / 32; g++) {
                unsigned m = mmask[g];
                while (m && cnt < K) {
                    int j = g * 32 + (__ffs(m) - 1);
                    m &= m - 1;
                    int s2 = sC[j], e2 = eC[j];
                    int w = e2 - s2;
                    bool cr = false;
                    if (t >= 1 && t <= w) cr = (s2e[s2 + t] > e2);          // tok in (s,e]
                    if (t < w) {
                        int v = e2s[s2 + t];                                 // tok in [s,e)
                        cr |= (v >= 0) && (v < s2);
                    }
                    unsigned b2 = __ballot_sync(0xFFFFFFFFu, cr);
                    if (b2 == 0) {
                        if (t == 0) {
                            if (e2 > s2e[s2]) s2e[s2] = e2;
                            int cur = e2s[e2];
                            if (cur == -1 || s2 < cur) e2s[e2] = s2;
                            g_sel[cC[j]] = 1;
                        }
                        cnt++;
                        __syncwarp();
                    }
                }
                if (cnt >= K) break;
            }
            if (t == 0) { sh_cnt = cnt; if (cnt >= K) sh_done = 1; }
        }
        __syncthreads();
    }
    if (t == 0) g_cnt = sh_cnt;
}

// ============================================================
// Kernel: compact selected, sort by (s*T+e, idx) via 1024-wide bitonic,
// emit [top_scores(k), top_idx(k), top_spans(k,2), valid(k)] as float32.
// ============================================================
__global__ void __launch_bounds__(1024, 1)
k_final(const int* __restrict__ spans, const float* __restrict__ scores,
        const int* __restrict__ pT, const int* __restrict__ pK,
        int N, float* __restrict__ out, int out_size) {
    __shared__ unsigned long long keys[1024];
    __shared__ int scnt;
    int t = threadIdx.x;
    keys[t] = 0xFFFFFFFFFFFFFFFFull;
    if (t == 0) scnt = 0;
    __syncthreads();

    int T = pT ? pT[0] : TMAX;
    for (int c = t; c < N; c += blockDim.x) {
        if (g_sel[c]) {
            int p = atomicAdd(&scnt, 1);
            if (p < 1024) {
                long long sk = (long long)spans[2 * c] * T + spans[2 * c + 1];
                keys[p] = ((unsigned long long)sk << 17) | (unsigned)c;
            }
        }
    }
    __syncthreads();

    // bitonic sort ascending (key embeds idx in low bits -> stable tie-break)
    for (int ks = 2; ks <= 1024; ks <<= 1) {
        for (int j = ks >> 1; j > 0; j >>= 1) {
            int ixj = t ^ j;
            if (ixj > t) {
                bool up = ((t & ks) == 0);
                unsigned long long a = keys[t], b = keys[ixj];
                if ((a > b) == up) { keys[t] = b; keys[ixj] = a; }
            }
            __syncthreads();
        }
    }

    int K = pK ? pK[0] : 819;
    int k_out = out_size / 5;         // layout: scores,k | idx,k | spans,2k | valid,k
    if (K > k_out) K = k_out;
    int cnt = g_cnt;
    if (cnt > K) cnt = K;
    for (int j = t; j < k_out; j += blockDim.x) {
        bool valid = (j < cnt);
        int c = valid ? (int)(keys[j] & 0x1FFFFull) : 0;
        float sc = valid ? scores[c] : 0.0f;
        int ss = valid ? spans[2 * c] : 0;
        int ee = valid ? spans[2 * c + 1] : 0;
        out[j]                   = sc;
        out[k_out + j]           = valid ? (float)c : 0.0f;
        out[2 * k_out + 2 * j]     = (float)ss;
        out[2 * k_out + 2 * j + 1] = (float)ee;
        out[4 * k_out + j]       = valid ? 1.0f : 0.0f;
    }
}

// ============================================================
// Launch: init -> 4x(hist,scan,scatter) -> greedy -> finalize (15 nodes)
// ============================================================
extern "C" void kernel_launch(void* const* d_in, const int* in_sizes, int n_in,
                              void* d_out, int out_size) {
    const int*   spans  = (const int*)d_in[0];
    const float* scores = (const float*)d_in[1];
    const float* mask   = (const float*)d_in[2];
    const int*   pT     = (n_in > 3) ? (const int*)d_in[3] : nullptr;
    const int*   pK     = (n_in > 4) ? (const int*)d_in[4] : nullptr;
    int N = in_sizes[1];  // span_mention_scores element count

    k_init<<<(N + 255) / 256, 256>>>(scores, mask, N);

    int srcIsA = 1;
    for (int p = 0; p < 4; p++) {
        int shift = 32 + 8 * p;
        k_hist<<<NB, 256>>>(srcIsA, N, shift);
        k_scan<<<1, 256>>>();
        k_scatter<<<NB, 256>>>(srcIsA, N, shift);
        srcIsA ^= 1;
    }
    // 4 passes: A->B->A->B->A, sorted order ends in g_bufA.

    k_greedy<<<1, CHUNK>>>(spans, pK, N);
    k_final<<<1, 1024>>>(spans, scores, pT, pK, N, (float*)d_out, out_size);
}

// round 6
// speedup vs baseline: 1.0277x; 1.0277x over previous
#include <cuda_runtime.h>
#include <stdint.h>
#include <limits.h>

// Problem-scale constants (dataset: T=2048, W=30, N=61440, k=819)
#define NMAX   61440
#define TMAX   2048
#define NB     60          // radix blocks; NB*CHUNK >= NMAX
#define CHUNK  1024

// ---- device-global scratch (no allocations allowed) ----
__device__ unsigned long long g_bufA[NMAX];
__device__ unsigned long long g_bufB[NMAX];
__device__ unsigned int       g_hist[256 * NB];
__device__ unsigned char      g_sel[NMAX];
__device__ int                g_cnt;

// span crossing: (a strictly starts inside b and ends after) either way
__device__ __forceinline__ bool spans_cross(int s1, int e1, int s2, int e2) {
    return (s1 < s2 && s2 <= e1 && e1 < e2) || (s2 < s1 && s1 <= e2 && e2 < e1);
}

// ============================================================
// Kernel 1: build sort keys (descending score+log(mask), tie -> ascending idx)
// key64 = (~sortable_asc(f)) << 32 | idx ; ascending radix sort gives order
// ============================================================
__global__ void k_init(const float* __restrict__ scores,
                       const float* __restrict__ mask, int N) {
    int i = blockIdx.x * blockDim.x + threadIdx.x;
    if (i < N) {
        float key = scores[i] + logf(mask[i]);
        unsigned b   = __float_as_uint(key);
        unsigned asc = (b & 0x80000000u) ? ~b : (b | 0x80000000u);
        unsigned dsc = ~asc;
        g_bufA[i] = ((unsigned long long)dsc << 32) | (unsigned)i;
        g_sel[i] = 0;
    }
    if (i == 0) g_cnt = 0;
}

// ============================================================
// LSD radix sort: bits [32..63], 4 passes x 8 bits, stable.
// ============================================================
__global__ void k_hist(int srcIsA, int N, int shift) {
    const unsigned long long* src = srcIsA ? g_bufA : g_bufB;
    __shared__ unsigned int h[256];
    int t = threadIdx.x;
    h[t] = 0;
    __syncthreads();
    int base = blockIdx.x * CHUNK;
    for (int j = t; j < CHUNK; j += 256) {
        int i = base + j;
        if (i < N) {
            unsigned d = (unsigned)(src[i] >> shift) & 255u;
            atomicAdd(&h[d], 1u);
        }
    }
    __syncthreads();
    g_hist[t * NB + blockIdx.x] = h[t];
}

__global__ void k_scan() {
    __shared__ unsigned int tot[256];
    int t = threadIdx.x;
    unsigned v[NB];
    unsigned run = 0;
    #pragma unroll
    for (int b = 0; b < NB; b++) v[b] = g_hist[t * NB + b];
    #pragma unroll
    for (int b = 0; b < NB; b++) { unsigned x = v[b]; v[b] = run; run += x; }
    tot[t] = run;
    __syncthreads();
    if (t == 0) {
        unsigned acc = 0;
        for (int i = 0; i < 256; i++) { unsigned x = tot[i]; tot[i] = acc; acc += x; }
    }
    __syncthreads();
    unsigned base = tot[t];
    #pragma unroll
    for (int b = 0; b < NB; b++) g_hist[t * NB + b] = base + v[b];
}

// Scatter with __match_any_sync stable rank (replaces O(t) serial rank loop)
__global__ void k_scatter(int srcIsA, int N, int shift) {
    const unsigned long long* src = srcIsA ? g_bufA : g_bufB;
    unsigned long long*       dst = srcIsA ? g_bufB : g_bufA;
    __shared__ unsigned int base[256];
    __shared__ unsigned int wh[8][256];   // per-warp digit counts -> prefixes
    int t  = threadIdx.x;
    int wp = t >> 5, ln = t & 31;
    unsigned ltm = (1u << ln) - 1u;
    base[t] = g_hist[t * NB + blockIdx.x];
    int cbase = blockIdx.x * CHUNK;

    for (int wv = 0; wv < CHUNK / 256; wv++) {
        // clear per-warp counts
        #pragma unroll
        for (int w = 0; w < 8; w++) wh[w][t] = 0;
        __syncthreads();

        int i = cbase + wv * 256 + t;
        bool ok = (i < N);
        unsigned long long v = 0ull;
        unsigned d = 0;
        int matchVal = ok ? 0 : (256 + ln);   // inactive lanes never group
        if (ok) {
            v = src[i];
            d = (unsigned)(v >> shift) & 255u;
            matchVal = (int)d;
        }
        unsigned mm = __match_any_sync(0xFFFFFFFFu, matchVal);
        int lr = __popc(mm & ltm);            // stable rank within warp
        if (ok && lr == 0) wh[wp][d] = __popc(mm);   // one leader per (warp,digit)
        __syncthreads();

        // thread t owns digit t: exclusive prefix across the 8 warps
        unsigned run = base[t];
        #pragma unroll
        for (int w = 0; w < 8; w++) { unsigned x = wh[w][t]; wh[w][t] = run; run += x; }
        base[t] = run;
        __syncthreads();

        if (ok) dst[wh[wp][d] + lr] = v;
        __syncthreads();
    }
}

// ============================================================
// Greedy non-crossing selection (exact, capped at k).
// Phase-1: 1024 threads prune candidates vs live tables (monotone -> final reject),
//          compact survivors in order.
// Phase-2: warp 0 processes survivors in groups of 32:
//   step A: parallel re-check vs LIVE tables (covers all accepts before this group)
//   step B: leader-elect resolution for in-group crossings, O(1) pairwise math,
//           tables updated in place on each accept.
// ============================================================
__global__ void __launch_bounds__(CHUNK, 1)
k_greedy(const int* __restrict__ spans, const int* __restrict__ pK, int N) {
    __shared__ int s2e[TMAX];         // max end per start; -1 unset
    __shared__ int e2s[TMAX];         // min start per end; INT_MAX unset
    __shared__ int sC[CHUNK], eC[CHUNK], cC[CHUNK];
    __shared__ int sList[CHUNK];      // survivor thread-ids in order
    __shared__ int wCnt[32], wOff[32];
    __shared__ int sh_cnt, sh_done, sh_S;

    const unsigned FULL = 0xFFFFFFFFu;
    int t = threadIdx.x;
    int wp = t >> 5, ln = t & 31;
    for (int i = t; i < TMAX; i += blockDim.x) { s2e[i] = -1; e2s[i] = INT_MAX; }
    if (t == 0) { sh_cnt = 0; sh_done = 0; }
    __syncthreads();

    int K = pK ? pK[0] : 819;
    int nch = (N + CHUNK - 1) / CHUNK;

    for (int ch = 0; ch < nch; ch++) {
        if (sh_done) break;
        int i = ch * CHUNK + t;
        bool maybe = false;
        int s = 0, e = 0, c = 0;
        if (i < N) {
            c = (int)(unsigned)(g_bufA[i] & 0xFFFFFFFFull);
            s = __ldg(&spans[2 * c]);
            e = __ldg(&spans[2 * c + 1]);
            bool cross = false;
            int w = e - s;
            for (int d = 1; d <= w; d++)
                if (s2e[s + d] > e) { cross = true; break; }
            if (!cross)
                for (int d = 0; d < w; d++)
                    if (e2s[s + d] < s) { cross = true; break; }
            maybe = !cross;
        }
        sC[t] = s; eC[t] = e; cC[t] = c;

        // ordered compaction of survivors
        unsigned bal = __ballot_sync(FULL, maybe);
        if (ln == 0) wCnt[wp] = __popc(bal);
        __syncthreads();
        if (t < 32) {
            int v = wCnt[t];
            int acc = v;
            #pragma unroll
            for (int o = 1; o < 32; o <<= 1) {
                int n = __shfl_up_sync(FULL, acc, o);
                if (t >= o) acc += n;
            }
            wOff[t] = acc - v;
            if (t == 31) sh_S = acc;
        }
        __syncthreads();
        if (maybe) sList[wOff[wp] + __popc(bal & ((1u << ln) - 1u))] = t;
        __syncthreads();

        // phase-2: warp 0 only
        if (t < 32) {
            int cnt = sh_cnt;
            int S = sh_S;
            for (int g = 0; g < S && cnt < K; g += 32) {
                int j = g + t;
                bool act = (j < S);
                int ti = act ? sList[j] : 0;
                int s1 = sC[ti], e1 = eC[ti], c1 = cC[ti];
                bool alive = false;
                if (act) {
                    bool cross = false;
                    int w = e1 - s1;
                    for (int d = 1; d <= w; d++)
                        if (s2e[s1 + d] > e1) { cross = true; break; }
                    if (!cross)
                        for (int d = 0; d < w; d++)
                            if (e2s[s1 + d] < s1) { cross = true; break; }
                    alive = !cross;
                }
                // step B: serial leader-elect within the group
                while (true) {
                    unsigned m = __ballot_sync(FULL, alive);
                    if (!m) break;
                    int lead = __ffs(m) - 1;
                    int pk = __shfl_sync(FULL, (s1 << 12) | e1, lead);
                    int s2 = pk >> 12, e2 = pk & 4095;
                    if (t == lead) {
                        if (e2 > s2e[s2]) s2e[s2] = e2;
                        if (s2 < e2s[e2]) e2s[e2] = s2;
                        g_sel[c1] = 1;
                        alive = false;
                    }
                    cnt++;
                    if (cnt >= K) { alive = false; }
                    else if (alive && spans_cross(s1, e1, s2, e2)) alive = false;
                    __syncwarp();
                }
            }
            if (t == 0) { sh_cnt = cnt; if (cnt >= K) sh_done = 1; }
        }
        __syncthreads();
    }
    if (t == 0) g_cnt = sh_cnt;
}

// ============================================================
// Finalize: compact selected, bitonic sort by (s*T+e, idx),
// emit [top_scores(k), top_idx(k), top_spans(k,2), valid(k)] as float32.
// ============================================================
__global__ void __launch_bounds__(1024, 1)
k_final(const int* __restrict__ spans, const float* __restrict__ scores,
        const int* __restrict__ pT, const int* __restrict__ pK,
        int N, float* __restrict__ out, int out_size) {
    __shared__ unsigned long long keys[1024];
    __shared__ int scnt;
    int t = threadIdx.x;
    keys[t] = 0xFFFFFFFFFFFFFFFFull;
    if (t == 0) scnt = 0;
    __syncthreads();

    int T = pT ? pT[0] : TMAX;
    for (int c = t; c < N; c += blockDim.x) {
        if (g_sel[c]) {
            int p = atomicAdd(&scnt, 1);
            if (p < 1024) {
                long long sk = (long long)spans[2 * c] * T + spans[2 * c + 1];
                keys[p] = ((unsigned long long)sk << 17) | (unsigned)c;
            }
        }
    }
    __syncthreads();

    for (int ks = 2; ks <= 1024; ks <<= 1) {
        for (int j = ks >> 1; j > 0; j >>= 1) {
            int ixj = t ^ j;
            if (ixj > t) {
                bool up = ((t & ks) == 0);
                unsigned long long a = keys[t], b = keys[ixj];
                if ((a > b) == up) { keys[t] = b; keys[ixj] = a; }
            }
            __syncthreads();
        }
    }

    int K = pK ? pK[0] : 819;
    int k_out = out_size / 5;
    if (K > k_out) K = k_out;
    int cnt = g_cnt;
    if (cnt > K) cnt = K;
    for (int j = t; j < k_out; j += blockDim.x) {
        bool valid = (j < cnt);
        int c = valid ? (int)(keys[j] & 0x1FFFFull) : 0;
        float sc = valid ? scores[c] : 0.0f;
        int ss = valid ? spans[2 * c] : 0;
        int ee = valid ? spans[2 * c + 1] : 0;
        out[j]                     = sc;
        out[k_out + j]             = valid ? (float)c : 0.0f;
        out[2 * k_out + 2 * j]     = (float)ss;
        out[2 * k_out + 2 * j + 1] = (float)ee;
        out[4 * k_out + j]         = valid ? 1.0f : 0.0f;
    }
}

// ============================================================
extern "C" void kernel_launch(void* const* d_in, const int* in_sizes, int n_in,
                              void* d_out, int out_size) {
    const int*   spans  = (const int*)d_in[0];
    const float* scores = (const float*)d_in[1];
    const float* mask   = (const float*)d_in[2];
    const int*   pT     = (n_in > 3) ? (const int*)d_in[3] : nullptr;
    const int*   pK     = (n_in > 4) ? (const int*)d_in[4] : nullptr;
    int N = in_sizes[1];

    k_init<<<(N + 255) / 256, 256>>>(scores, mask, N);

    int srcIsA = 1;
    for (int p = 0; p < 4; p++) {
        int shift = 32 + 8 * p;
        k_hist<<<NB, 256>>>(srcIsA, N, shift);
        k_scan<<<1, 256>>>();
        k_scatter<<<NB, 256>>>(srcIsA, N, shift);
        srcIsA ^= 1;
    }

    k_greedy<<<1, CHUNK>>>(spans, pK, N);
    k_final<<<1, 1024>>>(spans, scores, pT, pK, N, (float*)d_out, out_size);
}